// round 4
// baseline (speedup 1.0000x reference)
#include <cuda_runtime.h>
#include <cstddef>

// Problem constants (fixed shapes from reference)
#define B_IMG   8192
#define N_TOK   49
#define C_DIM   384
#define H_HEADS 12
#define HD      32
#define NWIN    1024
#define QKV_N   (3 * C_DIM)          // 1152
#define M_ROWS  (B_IMG * N_TOK)      // 401408

// Scratch (allocation-free: device globals)
__device__ float g_qkv[(size_t)M_ROWS * QKV_N];   // ~1.85 GB
__device__ float g_attn[(size_t)M_ROWS * C_DIM];  // ~617 MB

// ---------------------------------------------------------------------------
// Tiled fp32 GEMM with bias: C[M,N] = A[M,K] @ B[K,N] + bias[N]
// BM=BN=128, BK=8, 256 threads, 8x8 per-thread micro-tile.
// Requires M%128==0, N%128==0, K%8==0 (true for all calls here).
// ---------------------------------------------------------------------------
template <int BM, int BN, int BK>
__global__ __launch_bounds__(256, 2)
void sgemm_bias_kernel(int M, int N, int K,
                       const float* __restrict__ A,
                       const float* __restrict__ B,
                       const float* __restrict__ bias,
                       float* __restrict__ C)
{
    constexpr int TM = 8, TN = 8;
    __shared__ float As[BK][BM];
    __shared__ float Bs[BK][BN];

    const int tid  = threadIdx.x;                // 0..255
    const int tRow = tid / (BN / TN);            // 0..15
    const int tCol = tid % (BN / TN);            // 0..15
    const int rowBase = blockIdx.y * BM;
    const int colBase = blockIdx.x * BN;

    // A tile load mapping (one float4 per thread)
    const int aRow = tid / (BK / 4);             // 0..127
    const int aCol = (tid % (BK / 4)) * 4;       // 0 or 4
    // B tile load mapping (one float4 per thread)
    const int bRow = tid / (BN / 4);             // 0..7
    const int bCol = (tid % (BN / 4)) * 4;       // 0..124

    float acc[TM][TN] = {};
    float regM[TM], regN[TN];

    for (int k0 = 0; k0 < K; k0 += BK) {
        float4 a = *reinterpret_cast<const float4*>(
            &A[(size_t)(rowBase + aRow) * K + k0 + aCol]);
        As[aCol + 0][aRow] = a.x;
        As[aCol + 1][aRow] = a.y;
        As[aCol + 2][aRow] = a.z;
        As[aCol + 3][aRow] = a.w;
        *reinterpret_cast<float4*>(&Bs[bRow][bCol]) =
            *reinterpret_cast<const float4*>(
                &B[(size_t)(k0 + bRow) * N + colBase + bCol]);
        __syncthreads();

        #pragma unroll
        for (int k = 0; k < BK; k++) {
            #pragma unroll
            for (int i = 0; i < TM; i += 4)
                *reinterpret_cast<float4*>(&regM[i]) =
                    *reinterpret_cast<const float4*>(&As[k][tRow * TM + i]);
            #pragma unroll
            for (int j = 0; j < TN; j += 4)
                *reinterpret_cast<float4*>(&regN[j]) =
                    *reinterpret_cast<const float4*>(&Bs[k][tCol * TN + j]);
            #pragma unroll
            for (int i = 0; i < TM; i++)
                #pragma unroll
                for (int j = 0; j < TN; j++)
                    acc[i][j] = fmaf(regM[i], regN[j], acc[i][j]);
        }
        __syncthreads();
    }

    #pragma unroll
    for (int i = 0; i < TM; i++) {
        const int row = rowBase + tRow * TM + i;
        #pragma unroll
        for (int j = 0; j < TN; j += 4) {
            const int col = colBase + tCol * TN + j;
            float4 o;
            o.x = acc[i][j + 0] + bias[col + 0];
            o.y = acc[i][j + 1] + bias[col + 1];
            o.z = acc[i][j + 2] + bias[col + 2];
            o.w = acc[i][j + 3] + bias[col + 3];
            *reinterpret_cast<float4*>(&C[(size_t)row * N + col]) = o;
        }
    }
}

// ---------------------------------------------------------------------------
// Window attention: one block per (window b, head h).
// q,kT,v in smem; logits (49x49) + rel_bias + shift mask; warp softmax; AV.
// ---------------------------------------------------------------------------
__global__ __launch_bounds__(128)
void attn_kernel(const float* __restrict__ qkv,
                 const float* __restrict__ rel_bias,
                 const float* __restrict__ mask,
                 float* __restrict__ out)
{
    const int bh = blockIdx.x;
    const int b  = bh / H_HEADS;
    const int h  = bh % H_HEADS;
    const int tid  = threadIdx.x;     // 128 threads
    const int lane = tid & 31;
    const int warp = tid >> 5;

    __shared__ float sq[N_TOK][HD];          // q (pre-scaled)
    __shared__ float skT[HD][N_TOK + 3];     // k transposed, stride 52
    __shared__ float sv[N_TOK][HD];          // v
    __shared__ float lg[N_TOK][52];          // logits / probs

    const float scale = 0.1767766952966369f; // 1/sqrt(32)
    const size_t base = (size_t)b * N_TOK * QKV_N + (size_t)h * HD;

    for (int idx = tid; idx < N_TOK * HD; idx += 128) {
        const int n = idx >> 5, d = idx & 31;
        const float* p = qkv + base + (size_t)n * QKV_N;
        sq[n][d]  = p[d] * scale;
        skT[d][n] = p[C_DIM + d];
        sv[n][d]  = p[2 * C_DIM + d];
    }
    __syncthreads();

    const float* rb = rel_bias + (size_t)h * N_TOK * N_TOK;
    const float* mk = mask + (size_t)(b & (NWIN - 1)) * N_TOK * N_TOK;

    for (int e = tid; e < N_TOK * N_TOK; e += 128) {
        const int i = e / N_TOK;
        const int j = e - i * N_TOK;
        float s = 0.f;
        #pragma unroll
        for (int d = 0; d < HD; d++)
            s = fmaf(sq[i][d], skT[d][j], s);
        lg[i][j] = s + rb[e] + mk[e];
    }
    __syncthreads();

    // Row softmax: each warp handles rows warp, warp+4, ...
    for (int r = warp; r < N_TOK; r += 4) {
        const float v0 = lg[r][lane];
        const float v1 = (lane + 32 < N_TOK) ? lg[r][lane + 32] : -1e30f;
        float m = fmaxf(v0, v1);
        #pragma unroll
        for (int o = 16; o > 0; o >>= 1)
            m = fmaxf(m, __shfl_xor_sync(0xffffffffu, m, o));
        const float e0 = __expf(v0 - m);
        const float e1 = (lane + 32 < N_TOK) ? __expf(v1 - m) : 0.f;
        float s = e0 + e1;
        #pragma unroll
        for (int o = 16; o > 0; o >>= 1)
            s += __shfl_xor_sync(0xffffffffu, s, o);
        const float inv = 1.f / s;
        lg[r][lane] = e0 * inv;
        if (lane + 32 < N_TOK) lg[r][lane + 32] = e1 * inv;
    }
    __syncthreads();

    // out[i][d] = sum_j probs[i][j] * v[j][d]; coalesced store
    for (int e = tid; e < N_TOK * HD; e += 128) {
        const int i = e >> 5, d = e & 31;
        float s = 0.f;
        #pragma unroll
        for (int j = 0; j < N_TOK; j++)
            s = fmaf(lg[i][j], sv[j][d], s);
        out[((size_t)b * N_TOK + i) * C_DIM + h * HD + d] = s;
    }
}

// ---------------------------------------------------------------------------
// Launch: QKV GEMM -> attention -> proj GEMM
// Inputs (metadata order): x, mask, qkv_w, qkv_b, rel_bias, proj_w, proj_b
// ---------------------------------------------------------------------------
extern "C" void kernel_launch(void* const* d_in, const int* in_sizes, int n_in,
                              void* d_out, int out_size)
{
    const float* x        = (const float*)d_in[0];
    const float* mask     = (const float*)d_in[1];
    const float* qkv_w    = (const float*)d_in[2];
    const float* qkv_b    = (const float*)d_in[3];
    const float* rel_bias = (const float*)d_in[4];
    const float* proj_w   = (const float*)d_in[5];
    const float* proj_b   = (const float*)d_in[6];
    float* out = (float*)d_out;

    float *qkv = nullptr, *attn = nullptr;
    cudaGetSymbolAddress((void**)&qkv,  g_qkv);
    cudaGetSymbolAddress((void**)&attn, g_attn);

    // 1) QKV projection: (401408 x 384) @ (384 x 1152) + b
    dim3 g1(QKV_N / 128, M_ROWS / 128);
    sgemm_bias_kernel<128, 128, 8><<<g1, 256>>>(M_ROWS, QKV_N, C_DIM,
                                                x, qkv_w, qkv_b, qkv);

    // 2) Window attention per (b, h)
    attn_kernel<<<B_IMG * H_HEADS, 128>>>(qkv, rel_bias, mask, attn);

    // 3) Output projection: (401408 x 384) @ (384 x 384) + b
    dim3 g2(C_DIM / 128, M_ROWS / 128);
    sgemm_bias_kernel<128, 128, 8><<<g2, 256>>>(M_ROWS, C_DIM, C_DIM,
                                                attn, proj_w, proj_b, out);
}

// round 5
// speedup vs baseline: 2.1763x; 2.1763x over previous
#include <cuda_runtime.h>
#include <cstdint>
#include <cstddef>

// Problem constants (fixed shapes from reference)
#define B_IMG   8192
#define N_TOK   49
#define C_DIM   384
#define H_HEADS 12
#define HD      32
#define NWIN    1024
#define QKV_N   (3 * C_DIM)          // 1152
#define M_ROWS  (B_IMG * N_TOK)      // 401408

// Scratch (allocation-free: device globals)
__device__ float g_qkv[(size_t)M_ROWS * QKV_N];   // ~1.85 GB
__device__ float g_attn[(size_t)M_ROWS * C_DIM];  // ~617 MB

// ---------------------------------------------------------------------------
// Helpers
// ---------------------------------------------------------------------------
__device__ __forceinline__ void cp16(void* smem_dst, const void* gsrc) {
    uint32_t sa = (uint32_t)__cvta_generic_to_shared(smem_dst);
    asm volatile("cp.async.cg.shared.global [%0], [%1], 16;\n" :: "r"(sa), "l"(gsrc));
}
__device__ __forceinline__ uint32_t f2tf32(float f) {
    uint32_t u;
    asm("cvt.rna.tf32.f32 %0, %1;" : "=r"(u) : "f"(f));
    return u;
}
__device__ __forceinline__ void mma_tf32(float* c, const uint32_t* a, const uint32_t* b) {
    asm volatile(
        "mma.sync.aligned.m16n8k8.row.col.f32.tf32.tf32.f32 "
        "{%0,%1,%2,%3}, {%4,%5,%6,%7}, {%8,%9}, {%0,%1,%2,%3};\n"
        : "+f"(c[0]), "+f"(c[1]), "+f"(c[2]), "+f"(c[3])
        : "r"(a[0]), "r"(a[1]), "r"(a[2]), "r"(a[3]), "r"(b[0]), "r"(b[1]));
}

// ---------------------------------------------------------------------------
// TF32 tensor-core GEMM with bias: C[M,N] = A[M,K] @ B[K,N] + bias[N]
// BM=BN=128, BK=32, 256 threads = 8 warps (4 row x 2 col), warp tile 32x64.
// cp.async 2-stage pipeline. Requires M%128==0, N%128==0, K%32==0.
// Shared layout (dynamic):
//   As[2][128][36]  (A row-major, pad 4 -> conflict-free frag loads)
//   Bs[2][ 32][136] (B row-major, pad 8 -> conflict-free frag loads)
// ---------------------------------------------------------------------------
#define AS_STRIDE 36
#define BS_STRIDE 136
#define AS_STAGE  (128 * AS_STRIDE)
#define BS_STAGE  (32 * BS_STRIDE)
#define SMEM_FLOATS (2 * AS_STAGE + 2 * BS_STAGE)

__global__ __launch_bounds__(256, 2)
void tf32_gemm_bias_kernel(int M, int N, int K,
                           const float* __restrict__ A,
                           const float* __restrict__ B,
                           const float* __restrict__ bias,
                           float* __restrict__ C)
{
    extern __shared__ float smem[];
    float* As = smem;                    // [2][128][36]
    float* Bs = smem + 2 * AS_STAGE;     // [2][32][136]

    const int tid  = threadIdx.x;
    const int lane = tid & 31;
    const int warp = tid >> 5;
    const int wm   = warp & 3;           // 0..3 (row groups of 32)
    const int wn   = warp >> 2;          // 0..1 (col groups of 64)
    const int r    = lane >> 2;          // 0..7
    const int c    = lane & 3;           // 0..3

    const int rowBase = blockIdx.y * 128;
    const int colBase = blockIdx.x * 128;

    // Global->smem load mappings (16B each, 4 per thread per tile)
    const int aRow  = tid >> 3;          // 0..31  (+32*j)
    const int aCol4 = (tid & 7) * 4;     // 0..28
    const int bRow  = tid >> 5;          // 0..7   (+8*j)
    const int bCol4 = (tid & 31) * 4;    // 0..124

    const float* Abase = A + (size_t)(rowBase + aRow) * K + aCol4;
    const float* Bbase = B + (size_t)bRow * N + colBase + bCol4;

    float acc[2][8][4];
    #pragma unroll
    for (int mi = 0; mi < 2; mi++)
        #pragma unroll
        for (int ni = 0; ni < 8; ni++)
            #pragma unroll
            for (int t = 0; t < 4; t++) acc[mi][ni][t] = 0.f;

    const int nk = K / 32;

    // ---- prologue: stage 0 ----
    {
        #pragma unroll
        for (int j = 0; j < 4; j++)
            cp16(&As[(aRow + 32 * j) * AS_STRIDE + aCol4],
                 Abase + (size_t)(32 * j) * K);
        #pragma unroll
        for (int j = 0; j < 4; j++)
            cp16(&Bs[(bRow + 8 * j) * BS_STRIDE + bCol4],
                 Bbase + (size_t)(8 * j) * N);
        asm volatile("cp.async.commit_group;\n" ::);
    }

    for (int t = 0; t < nk; t++) {
        const int s = t & 1;
        if (t + 1 < nk) {
            const int s2 = (t + 1) & 1;
            const int k0 = (t + 1) * 32;
            #pragma unroll
            for (int j = 0; j < 4; j++)
                cp16(&As[s2 * AS_STAGE + (aRow + 32 * j) * AS_STRIDE + aCol4],
                     Abase + (size_t)(32 * j) * K + k0);
            #pragma unroll
            for (int j = 0; j < 4; j++)
                cp16(&Bs[s2 * BS_STAGE + (bRow + 8 * j) * BS_STRIDE + bCol4],
                     Bbase + (size_t)(k0 + 8 * j) * N);
            asm volatile("cp.async.commit_group;\n" ::);
            asm volatile("cp.async.wait_group 1;\n" ::);
        } else {
            asm volatile("cp.async.wait_group 0;\n" ::);
        }
        __syncthreads();

        const float* as = As + s * AS_STAGE;
        const float* bs = Bs + s * BS_STAGE;

        #pragma unroll
        for (int kk = 0; kk < 32; kk += 8) {
            uint32_t afr[2][4];
            #pragma unroll
            for (int mi = 0; mi < 2; mi++) {
                const int row = wm * 32 + mi * 16;
                afr[mi][0] = f2tf32(as[(row + r)     * AS_STRIDE + kk + c]);
                afr[mi][1] = f2tf32(as[(row + 8 + r) * AS_STRIDE + kk + c]);
                afr[mi][2] = f2tf32(as[(row + r)     * AS_STRIDE + kk + c + 4]);
                afr[mi][3] = f2tf32(as[(row + 8 + r) * AS_STRIDE + kk + c + 4]);
            }
            uint32_t bfr[8][2];
            #pragma unroll
            for (int ni = 0; ni < 8; ni++) {
                const int col = wn * 64 + ni * 8 + r;
                bfr[ni][0] = f2tf32(bs[(kk + c)     * BS_STRIDE + col]);
                bfr[ni][1] = f2tf32(bs[(kk + c + 4) * BS_STRIDE + col]);
            }
            #pragma unroll
            for (int mi = 0; mi < 2; mi++)
                #pragma unroll
                for (int ni = 0; ni < 8; ni++)
                    mma_tf32(acc[mi][ni], afr[mi], bfr[ni]);
        }
        __syncthreads();
    }

    // ---- epilogue: add bias, store float2 pairs ----
    #pragma unroll
    for (int ni = 0; ni < 8; ni++) {
        const int col = colBase + wn * 64 + ni * 8 + c * 2;
        const float bx = bias[col];
        const float by = bias[col + 1];
        #pragma unroll
        for (int mi = 0; mi < 2; mi++) {
            const int row0 = rowBase + wm * 32 + mi * 16 + r;
            float2 o0, o1;
            o0.x = acc[mi][ni][0] + bx;
            o0.y = acc[mi][ni][1] + by;
            o1.x = acc[mi][ni][2] + bx;
            o1.y = acc[mi][ni][3] + by;
            *reinterpret_cast<float2*>(&C[(size_t)row0 * N + col]) = o0;
            *reinterpret_cast<float2*>(&C[(size_t)(row0 + 8) * N + col]) = o1;
        }
    }
}

// ---------------------------------------------------------------------------
// Window attention: one block per (window b, head h). (unchanged, fp32)
// ---------------------------------------------------------------------------
__global__ __launch_bounds__(128)
void attn_kernel(const float* __restrict__ qkv,
                 const float* __restrict__ rel_bias,
                 const float* __restrict__ mask,
                 float* __restrict__ out)
{
    const int bh = blockIdx.x;
    const int b  = bh / H_HEADS;
    const int h  = bh % H_HEADS;
    const int tid  = threadIdx.x;     // 128 threads
    const int lane = tid & 31;
    const int warp = tid >> 5;

    __shared__ float sq[N_TOK][HD];          // q (pre-scaled)
    __shared__ float skT[HD][N_TOK + 3];     // k transposed, stride 52
    __shared__ float sv[N_TOK][HD];          // v
    __shared__ float lg[N_TOK][52];          // logits / probs

    const float scale = 0.1767766952966369f; // 1/sqrt(32)
    const size_t base = (size_t)b * N_TOK * QKV_N + (size_t)h * HD;

    for (int idx = tid; idx < N_TOK * HD; idx += 128) {
        const int n = idx >> 5, d = idx & 31;
        const float* p = qkv + base + (size_t)n * QKV_N;
        sq[n][d]  = p[d] * scale;
        skT[d][n] = p[C_DIM + d];
        sv[n][d]  = p[2 * C_DIM + d];
    }
    __syncthreads();

    const float* rb = rel_bias + (size_t)h * N_TOK * N_TOK;
    const float* mk = mask + (size_t)(b & (NWIN - 1)) * N_TOK * N_TOK;

    for (int e = tid; e < N_TOK * N_TOK; e += 128) {
        const int i = e / N_TOK;
        const int j = e - i * N_TOK;
        float s = 0.f;
        #pragma unroll
        for (int d = 0; d < HD; d++)
            s = fmaf(sq[i][d], skT[d][j], s);
        lg[i][j] = s + rb[e] + mk[e];
    }
    __syncthreads();

    for (int r = warp; r < N_TOK; r += 4) {
        const float v0 = lg[r][lane];
        const float v1 = (lane + 32 < N_TOK) ? lg[r][lane + 32] : -1e30f;
        float m = fmaxf(v0, v1);
        #pragma unroll
        for (int o = 16; o > 0; o >>= 1)
            m = fmaxf(m, __shfl_xor_sync(0xffffffffu, m, o));
        const float e0 = __expf(v0 - m);
        const float e1 = (lane + 32 < N_TOK) ? __expf(v1 - m) : 0.f;
        float s = e0 + e1;
        #pragma unroll
        for (int o = 16; o > 0; o >>= 1)
            s += __shfl_xor_sync(0xffffffffu, s, o);
        const float inv = 1.f / s;
        lg[r][lane] = e0 * inv;
        if (lane + 32 < N_TOK) lg[r][lane + 32] = e1 * inv;
    }
    __syncthreads();

    for (int e = tid; e < N_TOK * HD; e += 128) {
        const int i = e >> 5, d = e & 31;
        float s = 0.f;
        #pragma unroll
        for (int j = 0; j < N_TOK; j++)
            s = fmaf(lg[i][j], sv[j][d], s);
        out[((size_t)b * N_TOK + i) * C_DIM + h * HD + d] = s;
    }
}

// ---------------------------------------------------------------------------
// Launch: QKV GEMM -> attention -> proj GEMM
// Inputs (metadata order): x, mask, qkv_w, qkv_b, rel_bias, proj_w, proj_b
// ---------------------------------------------------------------------------
extern "C" void kernel_launch(void* const* d_in, const int* in_sizes, int n_in,
                              void* d_out, int out_size)
{
    const float* x        = (const float*)d_in[0];
    const float* mask     = (const float*)d_in[1];
    const float* qkv_w    = (const float*)d_in[2];
    const float* qkv_b    = (const float*)d_in[3];
    const float* rel_bias = (const float*)d_in[4];
    const float* proj_w   = (const float*)d_in[5];
    const float* proj_b   = (const float*)d_in[6];
    float* out = (float*)d_out;

    float *qkv = nullptr, *attn = nullptr;
    cudaGetSymbolAddress((void**)&qkv,  g_qkv);
    cudaGetSymbolAddress((void**)&attn, g_attn);

    const int smem_bytes = SMEM_FLOATS * 4;  // 71680
    static bool attr_set = false;
    if (!attr_set) {
        cudaFuncSetAttribute(tf32_gemm_bias_kernel,
                             cudaFuncAttributeMaxDynamicSharedMemorySize,
                             smem_bytes);
        attr_set = true;
    }

    // 1) QKV projection: (401408 x 384) @ (384 x 1152) + b
    dim3 g1(QKV_N / 128, M_ROWS / 128);
    tf32_gemm_bias_kernel<<<g1, 256, smem_bytes>>>(M_ROWS, QKV_N, C_DIM,
                                                   x, qkv_w, qkv_b, qkv);

    // 2) Window attention per (b, h)
    attn_kernel<<<B_IMG * H_HEADS, 128>>>(qkv, rel_bias, mask, attn);

    // 3) Output projection: (401408 x 384) @ (384 x 384) + b
    dim3 g2(C_DIM / 128, M_ROWS / 128);
    tf32_gemm_bias_kernel<<<g2, 256, smem_bytes>>>(M_ROWS, C_DIM, C_DIM,
                                                   attn, proj_w, proj_b, out);
}

// round 6
// speedup vs baseline: 2.2137x; 1.0172x over previous
#include <cuda_runtime.h>
#include <cstdint>
#include <cstddef>

// Problem constants (fixed shapes from reference)
#define B_IMG   8192
#define N_TOK   49
#define C_DIM   384
#define H_HEADS 12
#define HD      32
#define NWIN    1024
#define QKV_N   (3 * C_DIM)          // 1152
#define M_ROWS  (B_IMG * N_TOK)      // 401408

// Scratch (allocation-free: device globals)
__device__ float g_qkv[(size_t)M_ROWS * QKV_N];    // ~1.85 GB (fp32, exact)
__device__ float g_attn[(size_t)M_ROWS * C_DIM];   // ~617 MB (tf32-rounded)
__device__ float g_x[(size_t)M_ROWS * C_DIM];      // ~617 MB (tf32-rounded x)
__device__ float g_qkvw[(size_t)C_DIM * QKV_N];    // tf32-rounded weights
__device__ float g_projw[(size_t)C_DIM * C_DIM];

// ---------------------------------------------------------------------------
// Helpers
// ---------------------------------------------------------------------------
__device__ __forceinline__ void cp16(void* smem_dst, const void* gsrc) {
    uint32_t sa = (uint32_t)__cvta_generic_to_shared(smem_dst);
    asm volatile("cp.async.cg.shared.global [%0], [%1], 16;\n" :: "r"(sa), "l"(gsrc));
}
__device__ __forceinline__ uint32_t f2tf32(float f) {
    uint32_t u;
    asm("cvt.rna.tf32.f32 %0, %1;" : "=r"(u) : "f"(f));
    return u;
}
__device__ __forceinline__ float tf32r(float f) {
    return __uint_as_float(f2tf32(f));
}
__device__ __forceinline__ void mma_tf32(float* c, const uint32_t* a, const uint32_t* b) {
    asm volatile(
        "mma.sync.aligned.m16n8k8.row.col.f32.tf32.tf32.f32 "
        "{%0,%1,%2,%3}, {%4,%5,%6,%7}, {%8,%9}, {%0,%1,%2,%3};\n"
        : "+f"(c[0]), "+f"(c[1]), "+f"(c[2]), "+f"(c[3])
        : "r"(a[0]), "r"(a[1]), "r"(a[2]), "r"(a[3]), "r"(b[0]), "r"(b[1]));
}

// ---------------------------------------------------------------------------
// Elementwise RNA-round-to-tf32 (pre-pass; removes all cvts from GEMM loops)
// ---------------------------------------------------------------------------
__global__ __launch_bounds__(256)
void round_tf32_kernel(const float4* __restrict__ in, float4* __restrict__ out, int n4)
{
    int i = blockIdx.x * blockDim.x + threadIdx.x;
    if (i < n4) {
        float4 v = in[i];
        v.x = tf32r(v.x); v.y = tf32r(v.y); v.z = tf32r(v.z); v.w = tf32r(v.w);
        out[i] = v;
    }
}

// ---------------------------------------------------------------------------
// TF32 tensor-core GEMM with bias: C[M,N] = A[M,K] @ B[K,N] + bias[N]
// A and B must be PRE-ROUNDED to tf32 (low mantissa bits zero).
// BM=BN=128, BK=32, 256 threads = 8 warps (4 row x 2 col), warp tile 32x64.
// ---------------------------------------------------------------------------
#define AS_STRIDE 36
#define BS_STRIDE 136
#define AS_STAGE  (128 * AS_STRIDE)
#define BS_STAGE  (32 * BS_STRIDE)
#define SMEM_FLOATS (2 * AS_STAGE + 2 * BS_STAGE)

__global__ __launch_bounds__(256, 2)
void tf32_gemm_bias_kernel(int M, int N, int K,
                           const float* __restrict__ A,
                           const float* __restrict__ B,
                           const float* __restrict__ bias,
                           float* __restrict__ C)
{
    extern __shared__ float smem[];
    float* As = smem;                    // [2][128][36]
    float* Bs = smem + 2 * AS_STAGE;     // [2][32][136]

    const int tid  = threadIdx.x;
    const int lane = tid & 31;
    const int warp = tid >> 5;
    const int wm   = warp & 3;
    const int wn   = warp >> 2;
    const int r    = lane >> 2;
    const int c    = lane & 3;

    const int rowBase = blockIdx.y * 128;
    const int colBase = blockIdx.x * 128;

    const int aRow  = tid >> 3;
    const int aCol4 = (tid & 7) * 4;
    const int bRow  = tid >> 5;
    const int bCol4 = (tid & 31) * 4;

    const float* Abase = A + (size_t)(rowBase + aRow) * K + aCol4;
    const float* Bbase = B + (size_t)bRow * N + colBase + bCol4;

    float acc[2][8][4];
    #pragma unroll
    for (int mi = 0; mi < 2; mi++)
        #pragma unroll
        for (int ni = 0; ni < 8; ni++)
            #pragma unroll
            for (int t = 0; t < 4; t++) acc[mi][ni][t] = 0.f;

    const int nk = K / 32;

    {
        #pragma unroll
        for (int j = 0; j < 4; j++)
            cp16(&As[(aRow + 32 * j) * AS_STRIDE + aCol4],
                 Abase + (size_t)(32 * j) * K);
        #pragma unroll
        for (int j = 0; j < 4; j++)
            cp16(&Bs[(bRow + 8 * j) * BS_STRIDE + bCol4],
                 Bbase + (size_t)(8 * j) * N);
        asm volatile("cp.async.commit_group;\n" ::);
    }

    for (int t = 0; t < nk; t++) {
        const int s = t & 1;
        if (t + 1 < nk) {
            const int s2 = (t + 1) & 1;
            const int k0 = (t + 1) * 32;
            #pragma unroll
            for (int j = 0; j < 4; j++)
                cp16(&As[s2 * AS_STAGE + (aRow + 32 * j) * AS_STRIDE + aCol4],
                     Abase + (size_t)(32 * j) * K + k0);
            #pragma unroll
            for (int j = 0; j < 4; j++)
                cp16(&Bs[s2 * BS_STAGE + (bRow + 8 * j) * BS_STRIDE + bCol4],
                     Bbase + (size_t)(k0 + 8 * j) * N);
            asm volatile("cp.async.commit_group;\n" ::);
            asm volatile("cp.async.wait_group 1;\n" ::);
        } else {
            asm volatile("cp.async.wait_group 0;\n" ::);
        }
        __syncthreads();

        const float* as = As + s * AS_STAGE;
        const float* bs = Bs + s * BS_STAGE;

        #pragma unroll
        for (int kk = 0; kk < 32; kk += 8) {
            uint32_t afr[2][4];
            #pragma unroll
            for (int mi = 0; mi < 2; mi++) {
                const int row = wm * 32 + mi * 16;
                afr[mi][0] = __float_as_uint(as[(row + r)     * AS_STRIDE + kk + c]);
                afr[mi][1] = __float_as_uint(as[(row + 8 + r) * AS_STRIDE + kk + c]);
                afr[mi][2] = __float_as_uint(as[(row + r)     * AS_STRIDE + kk + c + 4]);
                afr[mi][3] = __float_as_uint(as[(row + 8 + r) * AS_STRIDE + kk + c + 4]);
            }
            uint32_t bfr[8][2];
            #pragma unroll
            for (int ni = 0; ni < 8; ni++) {
                const int col = wn * 64 + ni * 8 + r;
                bfr[ni][0] = __float_as_uint(bs[(kk + c)     * BS_STRIDE + col]);
                bfr[ni][1] = __float_as_uint(bs[(kk + c + 4) * BS_STRIDE + col]);
            }
            #pragma unroll
            for (int mi = 0; mi < 2; mi++)
                #pragma unroll
                for (int ni = 0; ni < 8; ni++)
                    mma_tf32(acc[mi][ni], afr[mi], bfr[ni]);
        }
        __syncthreads();
    }

    #pragma unroll
    for (int ni = 0; ni < 8; ni++) {
        const int col = colBase + wn * 64 + ni * 8 + c * 2;
        const float bx = bias[col];
        const float by = bias[col + 1];
        #pragma unroll
        for (int mi = 0; mi < 2; mi++) {
            const int row0 = rowBase + wm * 32 + mi * 16 + r;
            float2 o0, o1;
            o0.x = acc[mi][ni][0] + bx;
            o0.y = acc[mi][ni][1] + by;
            o1.x = acc[mi][ni][2] + bx;
            o1.y = acc[mi][ni][3] + by;
            *reinterpret_cast<float2*>(&C[(size_t)row0 * N + col]) = o0;
            *reinterpret_cast<float2*>(&C[(size_t)(row0 + 8) * N + col]) = o1;
        }
    }
}

// ---------------------------------------------------------------------------
// Tensor-core window attention: one block (4 warps) per (window b, head h).
// QK^T: split-tf32 (hi*hi + lo*hi + hi*lo) => fp32-equivalent logits.
// Softmax: warp-per-row in smem (probs RNA-rounded to tf32).
// AV: plain tf32 mma (v pre-rounded). Output stored tf32-rounded for proj GEMM.
// ---------------------------------------------------------------------------
#define SQ_STRIDE  36   // (4r+c)  conflict-free A frags
#define SKT_STRIDE 56   // (24c+r) conflict-free B frags
#define SV_STRIDE  40   // (8c+r)  conflict-free B frags
#define LG_STRIDE  60   // (28r+c) conflict-free A frags

// float offsets into dynamic smem
#define OFF_SQH  0
#define OFF_SQL  (OFF_SQH + 64 * SQ_STRIDE)
#define OFF_KTH  (OFF_SQL + 64 * SQ_STRIDE)
#define OFF_KTL  (OFF_KTH + HD * SKT_STRIDE)
#define OFF_SV   (OFF_KTL + HD * SKT_STRIDE)
#define OFF_LG   (OFF_SV  + 56 * SV_STRIDE)
#define ATTN_SMEM_FLOATS (OFF_LG + 64 * LG_STRIDE)   // 14272 floats = 57088 B

__global__ __launch_bounds__(128)
void attn_tc_kernel(const float* __restrict__ qkv,
                    const float* __restrict__ rel_bias,
                    const float* __restrict__ mask,
                    float* __restrict__ out)
{
    extern __shared__ float sm[];
    float* sq_hi  = sm + OFF_SQH;
    float* sq_lo  = sm + OFF_SQL;
    float* skt_hi = sm + OFF_KTH;
    float* skt_lo = sm + OFF_KTL;
    float* sv     = sm + OFF_SV;
    float* lg     = sm + OFF_LG;

    const int bh = blockIdx.x;
    const int b  = bh / H_HEADS;
    const int h  = bh % H_HEADS;
    const int tid  = threadIdx.x;
    const int lane = tid & 31;
    const int warp = tid >> 5;
    const int r  = lane >> 2;
    const int c  = lane & 3;
    const int cc = c * 2;
    const int m0 = warp * 16;

    const float scale = 0.1767766952966369f; // 1/sqrt(32)
    const size_t base = (size_t)b * N_TOK * QKV_N + (size_t)h * HD;

    // ---- Phase 1: stage q (split hi/lo, scaled), k^T (split), v (rounded) ----
    for (int idx = tid; idx < N_TOK * HD; idx += 128) {
        const int n = idx >> 5, d = idx & 31;
        const float* p = qkv + base + (size_t)n * QKV_N;
        const float qv = p[d] * scale;
        const float qh = tf32r(qv);
        sq_hi[n * SQ_STRIDE + d] = qh;
        sq_lo[n * SQ_STRIDE + d] = tf32r(qv - qh);
        const float kv = p[C_DIM + d];
        const float kh = tf32r(kv);
        skt_hi[d * SKT_STRIDE + n] = kh;
        skt_lo[d * SKT_STRIDE + n] = tf32r(kv - kh);
        sv[n * SV_STRIDE + d] = tf32r(p[2 * C_DIM + d]);
    }
    // zero v pad rows 49..55 (AV k-padding)
    for (int idx = tid; idx < 7 * SV_STRIDE; idx += 128)
        sv[N_TOK * SV_STRIDE + idx] = 0.f;
    __syncthreads();

    // ---- Phase 2: QK^T via split-tf32 mma (logits fp32-accurate) ----
    float lacc[7][4];
    #pragma unroll
    for (int nt = 0; nt < 7; nt++)
        #pragma unroll
        for (int t = 0; t < 4; t++) lacc[nt][t] = 0.f;

    #pragma unroll
    for (int kf = 0; kf < 4; kf++) {
        const int d0 = kf * 8;
        const int a0 = (m0 + r) * SQ_STRIDE + d0 + c;
        const int a8 = a0 + 8 * SQ_STRIDE;
        uint32_t ah[4], al[4];
        ah[0] = __float_as_uint(sq_hi[a0]);     ah[1] = __float_as_uint(sq_hi[a8]);
        ah[2] = __float_as_uint(sq_hi[a0 + 4]); ah[3] = __float_as_uint(sq_hi[a8 + 4]);
        al[0] = __float_as_uint(sq_lo[a0]);     al[1] = __float_as_uint(sq_lo[a8]);
        al[2] = __float_as_uint(sq_lo[a0 + 4]); al[3] = __float_as_uint(sq_lo[a8 + 4]);
        #pragma unroll
        for (int nt = 0; nt < 7; nt++) {
            const int bi = (d0 + c) * SKT_STRIDE + nt * 8 + r;
            uint32_t bhf[2], blf[2];
            bhf[0] = __float_as_uint(skt_hi[bi]);
            bhf[1] = __float_as_uint(skt_hi[bi + 4 * SKT_STRIDE]);
            blf[0] = __float_as_uint(skt_lo[bi]);
            blf[1] = __float_as_uint(skt_lo[bi + 4 * SKT_STRIDE]);
            mma_tf32(lacc[nt], ah, bhf);
            mma_tf32(lacc[nt], al, bhf);
            mma_tf32(lacc[nt], ah, blf);
        }
    }

    // epilogue: + rel_bias + mask -> lg (only valid rows/cols)
    {
        const float* rb = rel_bias + (size_t)h * N_TOK * N_TOK;
        const float* mk = mask + (size_t)(b & (NWIN - 1)) * N_TOK * N_TOK;
        const int rowA = m0 + r, rowB = m0 + 8 + r;
        #pragma unroll
        for (int nt = 0; nt < 7; nt++) {
            const int col = nt * 8 + cc;
            if (col < N_TOK) {
                if (rowA < N_TOK) {
                    const int e = rowA * N_TOK + col;
                    lg[rowA * LG_STRIDE + col] = lacc[nt][0] + rb[e] + mk[e];
                    if (col + 1 < N_TOK)
                        lg[rowA * LG_STRIDE + col + 1] = lacc[nt][1] + rb[e + 1] + mk[e + 1];
                }
                if (rowB < N_TOK) {
                    const int e = rowB * N_TOK + col;
                    lg[rowB * LG_STRIDE + col] = lacc[nt][2] + rb[e] + mk[e];
                    if (col + 1 < N_TOK)
                        lg[rowB * LG_STRIDE + col + 1] = lacc[nt][3] + rb[e + 1] + mk[e + 1];
                }
            }
        }
    }
    __syncthreads();

    // ---- Phase 3: softmax (warp per row); probs rounded to tf32; pad zeroed ----
    for (int row = warp; row < N_TOK; row += 4) {
        float* lrow = lg + row * LG_STRIDE;
        const float v0 = lrow[lane];
        const bool has1 = (lane + 32) < N_TOK;
        const float v1 = has1 ? lrow[lane + 32] : -1e30f;
        float m = fmaxf(v0, v1);
        #pragma unroll
        for (int o = 16; o > 0; o >>= 1)
            m = fmaxf(m, __shfl_xor_sync(0xffffffffu, m, o));
        const float e0 = __expf(v0 - m);
        const float e1 = has1 ? __expf(v1 - m) : 0.f;
        float s = e0 + e1;
        #pragma unroll
        for (int o = 16; o > 0; o >>= 1)
            s += __shfl_xor_sync(0xffffffffu, s, o);
        const float inv = 1.f / s;
        lrow[lane] = tf32r(e0 * inv);
        if (has1)                 lrow[lane + 32] = tf32r(e1 * inv);
        else if (lane + 32 < 56)  lrow[lane + 32] = 0.f;   // zero k-pad cols 49..55
    }
    __syncthreads();

    // ---- Phase 4: AV via tf32 mma; store tf32-rounded for proj GEMM ----
    float oacc[4][4];
    #pragma unroll
    for (int nt = 0; nt < 4; nt++)
        #pragma unroll
        for (int t = 0; t < 4; t++) oacc[nt][t] = 0.f;

    #pragma unroll
    for (int kf = 0; kf < 7; kf++) {
        const int k0 = kf * 8;
        const int ai = (m0 + r) * LG_STRIDE + k0 + c;
        uint32_t a[4];
        a[0] = __float_as_uint(lg[ai]);
        a[1] = __float_as_uint(lg[ai + 8 * LG_STRIDE]);
        a[2] = __float_as_uint(lg[ai + 4]);
        a[3] = __float_as_uint(lg[ai + 8 * LG_STRIDE + 4]);
        #pragma unroll
        for (int nt = 0; nt < 4; nt++) {
            const int bi = (k0 + c) * SV_STRIDE + nt * 8 + r;
            uint32_t bb[2];
            bb[0] = __float_as_uint(sv[bi]);
            bb[1] = __float_as_uint(sv[bi + 4 * SV_STRIDE]);
            mma_tf32(oacc[nt], a, bb);
        }
    }

    {
        const int rowA = m0 + r, rowB = m0 + 8 + r;
        #pragma unroll
        for (int nt = 0; nt < 4; nt++) {
            const int col = nt * 8 + cc;
            if (rowA < N_TOK) {
                float2 v; v.x = tf32r(oacc[nt][0]); v.y = tf32r(oacc[nt][1]);
                *reinterpret_cast<float2*>(
                    &out[((size_t)b * N_TOK + rowA) * C_DIM + h * HD + col]) = v;
            }
            if (rowB < N_TOK) {
                float2 v; v.x = tf32r(oacc[nt][2]); v.y = tf32r(oacc[nt][3]);
                *reinterpret_cast<float2*>(
                    &out[((size_t)b * N_TOK + rowB) * C_DIM + h * HD + col]) = v;
            }
        }
    }
}

// ---------------------------------------------------------------------------
// Launch: round x/w -> QKV GEMM -> TC attention -> proj GEMM
// Inputs (metadata order): x, mask, qkv_w, qkv_b, rel_bias, proj_w, proj_b
// ---------------------------------------------------------------------------
extern "C" void kernel_launch(void* const* d_in, const int* in_sizes, int n_in,
                              void* d_out, int out_size)
{
    const float* x        = (const float*)d_in[0];
    const float* mask     = (const float*)d_in[1];
    const float* qkv_w    = (const float*)d_in[2];
    const float* qkv_b    = (const float*)d_in[3];
    const float* rel_bias = (const float*)d_in[4];
    const float* proj_w   = (const float*)d_in[5];
    const float* proj_b   = (const float*)d_in[6];
    float* out = (float*)d_out;

    float *qkv = nullptr, *attn = nullptr, *xr = nullptr, *qw = nullptr, *pw = nullptr;
    cudaGetSymbolAddress((void**)&qkv,  g_qkv);
    cudaGetSymbolAddress((void**)&attn, g_attn);
    cudaGetSymbolAddress((void**)&xr,   g_x);
    cudaGetSymbolAddress((void**)&qw,   g_qkvw);
    cudaGetSymbolAddress((void**)&pw,   g_projw);

    const int gemm_smem = SMEM_FLOATS * 4;        // 71680
    const int attn_smem = ATTN_SMEM_FLOATS * 4;   // 57088
    static bool attr_set = false;
    if (!attr_set) {
        cudaFuncSetAttribute(tf32_gemm_bias_kernel,
                             cudaFuncAttributeMaxDynamicSharedMemorySize, gemm_smem);
        cudaFuncSetAttribute(attn_tc_kernel,
                             cudaFuncAttributeMaxDynamicSharedMemorySize, attn_smem);
        attr_set = true;
    }

    // 0) Pre-round operands to tf32 (hoists cvt out of GEMM mainloops)
    {
        const int n4x = (int)((size_t)M_ROWS * C_DIM / 4);      // 38535168
        round_tf32_kernel<<<n4x / 256, 256>>>((const float4*)x, (float4*)xr, n4x);
        const int n4q = C_DIM * QKV_N / 4;                      // 110592
        round_tf32_kernel<<<(n4q + 255) / 256, 256>>>((const float4*)qkv_w, (float4*)qw, n4q);
        const int n4p = C_DIM * C_DIM / 4;                      // 36864
        round_tf32_kernel<<<(n4p + 255) / 256, 256>>>((const float4*)proj_w, (float4*)pw, n4p);
    }

    // 1) QKV projection: (401408 x 384) @ (384 x 1152) + b
    dim3 g1(QKV_N / 128, M_ROWS / 128);
    tf32_gemm_bias_kernel<<<g1, 256, gemm_smem>>>(M_ROWS, QKV_N, C_DIM,
                                                  xr, qw, qkv_b, qkv);

    // 2) Tensor-core window attention per (b, h)
    attn_tc_kernel<<<B_IMG * H_HEADS, 128, attn_smem>>>(qkv, rel_bias, mask, attn);

    // 3) Output projection: (401408 x 384) @ (384 x 384) + b
    dim3 g2(C_DIM / 128, M_ROWS / 128);
    tf32_gemm_bias_kernel<<<g2, 256, gemm_smem>>>(M_ROWS, C_DIM, C_DIM,
                                                  attn, proj_w ? pw : pw, proj_b, out);
}

// round 11
// speedup vs baseline: 2.7963x; 1.2632x over previous
#include <cuda_runtime.h>
#include <cstdint>
#include <cstddef>

// Problem constants (fixed shapes from reference)
#define B_IMG   8192
#define N_TOK   49
#define C_DIM   384
#define H_HEADS 12
#define HD      32
#define NWIN    1024
#define QKV_N   (3 * C_DIM)          // 1152
#define M_ROWS  (B_IMG * N_TOK)      // 401408

// Scratch (allocation-free: device globals)
__device__ float g_qkv[(size_t)M_ROWS * QKV_N];    // ~1.85 GB (fp32, exact)
__device__ float g_attn[(size_t)M_ROWS * C_DIM];   // ~617 MB (tf32-rounded)
__device__ float g_x[(size_t)M_ROWS * C_DIM];      // ~617 MB (tf32-rounded x)
__device__ float g_qkvw[(size_t)C_DIM * QKV_N];    // tf32-rounded weights
__device__ float g_projw[(size_t)C_DIM * C_DIM];

// ---------------------------------------------------------------------------
// Helpers
// ---------------------------------------------------------------------------
__device__ __forceinline__ void cp16(void* smem_dst, const void* gsrc) {
    uint32_t sa = (uint32_t)__cvta_generic_to_shared(smem_dst);
    asm volatile("cp.async.cg.shared.global [%0], [%1], 16;\n" :: "r"(sa), "l"(gsrc));
}
__device__ __forceinline__ uint32_t f2tf32(float f) {
    uint32_t u;
    asm("cvt.rna.tf32.f32 %0, %1;" : "=r"(u) : "f"(f));
    return u;
}
__device__ __forceinline__ float tf32r(float f) {
    return __uint_as_float(f2tf32(f));
}
__device__ __forceinline__ void mma_tf32(float* c, const uint32_t* a, const uint32_t* b) {
    asm volatile(
        "mma.sync.aligned.m16n8k8.row.col.f32.tf32.tf32.f32 "
        "{%0,%1,%2,%3}, {%4,%5,%6,%7}, {%8,%9}, {%0,%1,%2,%3};\n"
        : "+f"(c[0]), "+f"(c[1]), "+f"(c[2]), "+f"(c[3])
        : "r"(a[0]), "r"(a[1]), "r"(a[2]), "r"(a[3]), "r"(b[0]), "r"(b[1]));
}

// ---------------------------------------------------------------------------
// Elementwise RNA-round-to-tf32 (pre-pass; removes all cvts from GEMM loops)
// ---------------------------------------------------------------------------
__global__ __launch_bounds__(256)
void round_tf32_kernel(const float4* __restrict__ in, float4* __restrict__ out, int n4)
{
    int i = blockIdx.x * blockDim.x + threadIdx.x;
    if (i < n4) {
        float4 v = in[i];
        v.x = tf32r(v.x); v.y = tf32r(v.y); v.z = tf32r(v.z); v.w = tf32r(v.w);
        out[i] = v;
    }
}

// ---------------------------------------------------------------------------
// TF32 tensor-core GEMM with bias: C[M,N] = A[M,K] @ B[K,N] + bias[N]
// A and B must be PRE-ROUNDED to tf32 (low mantissa bits zero).
// BM=BN=128, BK=32, 256 threads = 8 warps (4 row x 2 col), warp tile 32x64.
// ---------------------------------------------------------------------------
#define AS_STRIDE 36
#define BS_STRIDE 136
#define AS_STAGE  (128 * AS_STRIDE)
#define BS_STAGE  (32 * BS_STRIDE)
#define SMEM_FLOATS (2 * AS_STAGE + 2 * BS_STAGE)

__global__ __launch_bounds__(256, 2)
void tf32_gemm_bias_kernel(int M, int N, int K,
                           const float* __restrict__ A,
                           const float* __restrict__ B,
                           const float* __restrict__ bias,
                           float* __restrict__ C)
{
    extern __shared__ float smem[];
    float* As = smem;                    // [2][128][36]
    float* Bs = smem + 2 * AS_STAGE;     // [2][32][136]

    const int tid  = threadIdx.x;
    const int lane = tid & 31;
    const int warp = tid >> 5;
    const int wm   = warp & 3;
    const int wn   = warp >> 2;
    const int r    = lane >> 2;
    const int c    = lane & 3;

    const int rowBase = blockIdx.y * 128;
    const int colBase = blockIdx.x * 128;

    const int aRow  = tid >> 3;
    const int aCol4 = (tid & 7) * 4;
    const int bRow  = tid >> 5;
    const int bCol4 = (tid & 31) * 4;

    const float* Abase = A + (size_t)(rowBase + aRow) * K + aCol4;
    const float* Bbase = B + (size_t)bRow * N + colBase + bCol4;

    float acc[2][8][4];
    #pragma unroll
    for (int mi = 0; mi < 2; mi++)
        #pragma unroll
        for (int ni = 0; ni < 8; ni++)
            #pragma unroll
            for (int t = 0; t < 4; t++) acc[mi][ni][t] = 0.f;

    const int nk = K / 32;

    {
        #pragma unroll
        for (int j = 0; j < 4; j++)
            cp16(&As[(aRow + 32 * j) * AS_STRIDE + aCol4],
                 Abase + (size_t)(32 * j) * K);
        #pragma unroll
        for (int j = 0; j < 4; j++)
            cp16(&Bs[(bRow + 8 * j) * BS_STRIDE + bCol4],
                 Bbase + (size_t)(8 * j) * N);
        asm volatile("cp.async.commit_group;\n" ::);
    }

    for (int t = 0; t < nk; t++) {
        const int s = t & 1;
        if (t + 1 < nk) {
            const int s2 = (t + 1) & 1;
            const int k0 = (t + 1) * 32;
            #pragma unroll
            for (int j = 0; j < 4; j++)
                cp16(&As[s2 * AS_STAGE + (aRow + 32 * j) * AS_STRIDE + aCol4],
                     Abase + (size_t)(32 * j) * K + k0);
            #pragma unroll
            for (int j = 0; j < 4; j++)
                cp16(&Bs[s2 * BS_STAGE + (bRow + 8 * j) * BS_STRIDE + bCol4],
                     Bbase + (size_t)(k0 + 8 * j) * N);
            asm volatile("cp.async.commit_group;\n" ::);
            asm volatile("cp.async.wait_group 1;\n" ::);
        } else {
            asm volatile("cp.async.wait_group 0;\n" ::);
        }
        __syncthreads();

        const float* as = As + s * AS_STAGE;
        const float* bs = Bs + s * BS_STAGE;

        #pragma unroll
        for (int kk = 0; kk < 32; kk += 8) {
            uint32_t afr[2][4];
            #pragma unroll
            for (int mi = 0; mi < 2; mi++) {
                const int row = wm * 32 + mi * 16;
                afr[mi][0] = __float_as_uint(as[(row + r)     * AS_STRIDE + kk + c]);
                afr[mi][1] = __float_as_uint(as[(row + 8 + r) * AS_STRIDE + kk + c]);
                afr[mi][2] = __float_as_uint(as[(row + r)     * AS_STRIDE + kk + c + 4]);
                afr[mi][3] = __float_as_uint(as[(row + 8 + r) * AS_STRIDE + kk + c + 4]);
            }
            uint32_t bfr[8][2];
            #pragma unroll
            for (int ni = 0; ni < 8; ni++) {
                const int col = wn * 64 + ni * 8 + r;
                bfr[ni][0] = __float_as_uint(bs[(kk + c)     * BS_STRIDE + col]);
                bfr[ni][1] = __float_as_uint(bs[(kk + c + 4) * BS_STRIDE + col]);
            }
            #pragma unroll
            for (int mi = 0; mi < 2; mi++)
                #pragma unroll
                for (int ni = 0; ni < 8; ni++)
                    mma_tf32(acc[mi][ni], afr[mi], bfr[ni]);
        }
        __syncthreads();
    }

    #pragma unroll
    for (int ni = 0; ni < 8; ni++) {
        const int col = colBase + wn * 64 + ni * 8 + c * 2;
        const float bx = bias[col];
        const float by = bias[col + 1];
        #pragma unroll
        for (int mi = 0; mi < 2; mi++) {
            const int row0 = rowBase + wm * 32 + mi * 16 + r;
            float2 o0, o1;
            o0.x = acc[mi][ni][0] + bx;
            o0.y = acc[mi][ni][1] + by;
            o1.x = acc[mi][ni][2] + bx;
            o1.y = acc[mi][ni][3] + by;
            *reinterpret_cast<float2*>(&C[(size_t)row0 * N + col]) = o0;
            *reinterpret_cast<float2*>(&C[(size_t)(row0 + 8) * N + col]) = o1;
        }
    }
}

// ---------------------------------------------------------------------------
// Tensor-core window attention v2: one block (8 warps, 256 thr) per (b, h).
// Warp grid: wm = warp&3 selects m16 row tile; wn2 = warp>>2 splits N columns.
// - float4 gmem loads for q/k/v; mask+rel_bias preloaded into lg (overlaps MMA)
// - QK^T: split-Q tf32 (q_hi*k + q_lo*k), k rounded once => logit err ~2.4e-4
// - softmax warp-per-row; probs tf32-rounded; AV plain tf32.
// NOTE: LG_STRIDE must be >= 56 (AV reads k-cols 0..55 incl. zero pad) — 60.
// ---------------------------------------------------------------------------
#define SQ_STRIDE  36   // A-frag: {r*36+c} distinct mod 32
#define SKT_STRIDE 56   // B-frag: {c*56+r} distinct mod 32 (56 ≡ 24)
#define SV_STRIDE  40   // B-frag: {c*40+r} distinct mod 32 (40 ≡ 8)
#define LG_STRIDE  60   // A-frag: {r*60+c} distinct mod 32 (60 ≡ 28); >=56!

#define OFF_SQH  0
#define OFF_SQL  (OFF_SQH + 64 * SQ_STRIDE)                 // 2304
#define OFF_KT   (OFF_SQL + 64 * SQ_STRIDE)                 // 4608
#define OFF_SV   (OFF_KT  + HD * SKT_STRIDE)                // 6400
#define OFF_LG   (OFF_SV  + 56 * SV_STRIDE)                 // 8640
#define ATTN_SMEM_FLOATS (OFF_LG + 64 * LG_STRIDE)          // 12480 fl = 49920 B

__global__ __launch_bounds__(256)
void attn_tc_kernel(const float* __restrict__ qkv,
                    const float* __restrict__ rel_bias,
                    const float* __restrict__ mask,
                    float* __restrict__ out)
{
    extern __shared__ float sm[];
    float* sq_hi = sm + OFF_SQH;
    float* sq_lo = sm + OFF_SQL;
    float* skt   = sm + OFF_KT;
    float* sv    = sm + OFF_SV;
    float* lg    = sm + OFF_LG;

    const int bh = blockIdx.x;
    const int b  = bh / H_HEADS;
    const int h  = bh % H_HEADS;
    const int tid  = threadIdx.x;     // 256
    const int lane = tid & 31;
    const int warp = tid >> 5;        // 0..7
    const int wm   = warp & 3;
    const int wn2  = warp >> 2;       // 0/1
    const int r  = lane >> 2;
    const int c  = lane & 3;
    const int m0 = wm * 16;

    const float scale = 0.1767766952966369f; // 1/sqrt(32)
    const size_t base = (size_t)b * N_TOK * QKV_N + (size_t)h * HD;

    // ---- Phase 1a: stage q (split hi/lo, scaled), k^T (rounded), v (rounded)
    #pragma unroll 2
    for (int i = tid; i < N_TOK * 8; i += 256) {
        const int n  = i >> 3;
        const int d  = (i & 7) * 4;
        const float* row = qkv + base + (size_t)n * QKV_N;
        const float4 qv = *reinterpret_cast<const float4*>(row + d);
        const float4 kv = *reinterpret_cast<const float4*>(row + C_DIM + d);
        const float4 vv = *reinterpret_cast<const float4*>(row + 2 * C_DIM + d);

        float4 qh, ql;
        {
            float s;
            s = qv.x * scale; qh.x = tf32r(s); ql.x = tf32r(s - qh.x);
            s = qv.y * scale; qh.y = tf32r(s); ql.y = tf32r(s - qh.y);
            s = qv.z * scale; qh.z = tf32r(s); ql.z = tf32r(s - qh.z);
            s = qv.w * scale; qh.w = tf32r(s); ql.w = tf32r(s - qh.w);
        }
        *reinterpret_cast<float4*>(&sq_hi[n * SQ_STRIDE + d]) = qh;
        *reinterpret_cast<float4*>(&sq_lo[n * SQ_STRIDE + d]) = ql;

        skt[(d + 0) * SKT_STRIDE + n] = tf32r(kv.x);
        skt[(d + 1) * SKT_STRIDE + n] = tf32r(kv.y);
        skt[(d + 2) * SKT_STRIDE + n] = tf32r(kv.z);
        skt[(d + 3) * SKT_STRIDE + n] = tf32r(kv.w);

        float4 vr;
        vr.x = tf32r(vv.x); vr.y = tf32r(vv.y);
        vr.z = tf32r(vv.z); vr.w = tf32r(vv.w);
        *reinterpret_cast<float4*>(&sv[n * SV_STRIDE + d]) = vr;
    }
    // zero v pad rows 49..55 (AV k-padding)
    for (int j = tid; j < 7 * SV_STRIDE; j += 256)
        sv[N_TOK * SV_STRIDE + j] = 0.f;

    // ---- Phase 1b: preload lg = rel_bias + mask (overlaps with staging) ----
    {
        const float* rb = rel_bias + (size_t)h * N_TOK * N_TOK;
        const float* mk = mask + (size_t)(b & (NWIN - 1)) * N_TOK * N_TOK;
        #pragma unroll 2
        for (int e = tid; e < N_TOK * N_TOK; e += 256) {
            const int row = e / N_TOK;
            const int col = e - row * N_TOK;
            lg[row * LG_STRIDE + col] = rb[e] + mk[e];
        }
    }
    __syncthreads();

    // ---- Phase 2: QK^T (split-Q tf32), accumulate into lg ----
    const int ntb = wn2 * 4;            // 0 or 4
    const int ntn = wn2 ? 3 : 4;        // tiles handled by this warp
    float lacc[4][4];
    #pragma unroll
    for (int nti = 0; nti < 4; nti++)
        #pragma unroll
        for (int t = 0; t < 4; t++) lacc[nti][t] = 0.f;

    #pragma unroll
    for (int kf = 0; kf < 4; kf++) {
        const int d0 = kf * 8;
        const int a0 = (m0 + r) * SQ_STRIDE + d0 + c;
        const int a8 = a0 + 8 * SQ_STRIDE;
        uint32_t ah[4], al[4];
        ah[0] = __float_as_uint(sq_hi[a0]);     ah[1] = __float_as_uint(sq_hi[a8]);
        ah[2] = __float_as_uint(sq_hi[a0 + 4]); ah[3] = __float_as_uint(sq_hi[a8 + 4]);
        al[0] = __float_as_uint(sq_lo[a0]);     al[1] = __float_as_uint(sq_lo[a8]);
        al[2] = __float_as_uint(sq_lo[a0 + 4]); al[3] = __float_as_uint(sq_lo[a8 + 4]);
        #pragma unroll
        for (int nti = 0; nti < 4; nti++) {
            if (nti < ntn) {
                const int bi = (d0 + c) * SKT_STRIDE + (ntb + nti) * 8 + r;
                uint32_t bf[2];
                bf[0] = __float_as_uint(skt[bi]);
                bf[1] = __float_as_uint(skt[bi + 4 * SKT_STRIDE]);
                mma_tf32(lacc[nti], ah, bf);
                mma_tf32(lacc[nti], al, bf);
            }
        }
    }

    // epilogue: lg += lacc (lg already holds rel_bias + mask)
    {
        const int rowA = m0 + r, rowB = m0 + 8 + r;
        #pragma unroll
        for (int nti = 0; nti < 4; nti++) {
            if (nti < ntn) {
                const int col = (ntb + nti) * 8 + c * 2;
                if (col < N_TOK) {
                    if (rowA < N_TOK) {
                        float* p = &lg[rowA * LG_STRIDE + col];
                        p[0] += lacc[nti][0];
                        if (col + 1 < N_TOK) p[1] += lacc[nti][1];
                    }
                    if (rowB < N_TOK) {
                        float* p = &lg[rowB * LG_STRIDE + col];
                        p[0] += lacc[nti][2];
                        if (col + 1 < N_TOK) p[1] += lacc[nti][3];
                    }
                }
            }
        }
    }
    __syncthreads();

    // ---- Phase 3: softmax (warp per row, 8 warps); probs tf32; pad zeroed ----
    for (int row = warp; row < N_TOK; row += 8) {
        float* lrow = lg + row * LG_STRIDE;
        const float v0 = lrow[lane];
        const bool has1 = (lane + 32) < N_TOK;
        const float v1 = has1 ? lrow[lane + 32] : -1e30f;
        float m = fmaxf(v0, v1);
        #pragma unroll
        for (int o = 16; o > 0; o >>= 1)
            m = fmaxf(m, __shfl_xor_sync(0xffffffffu, m, o));
        const float e0 = __expf(v0 - m);
        const float e1 = has1 ? __expf(v1 - m) : 0.f;
        float s = e0 + e1;
        #pragma unroll
        for (int o = 16; o > 0; o >>= 1)
            s += __shfl_xor_sync(0xffffffffu, s, o);
        const float inv = 1.f / s;
        lrow[lane] = tf32r(e0 * inv);
        if (has1)                 lrow[lane + 32] = tf32r(e1 * inv);
        else if (lane + 32 < 56)  lrow[lane + 32] = 0.f;   // zero k-pad cols
    }
    __syncthreads();

    // ---- Phase 4: AV via tf32 mma (2 d-tiles per warp) ----
    float oacc[2][4];
    #pragma unroll
    for (int j = 0; j < 2; j++)
        #pragma unroll
        for (int t = 0; t < 4; t++) oacc[j][t] = 0.f;

    #pragma unroll
    for (int kf = 0; kf < 7; kf++) {
        const int k0 = kf * 8;
        const int ai = (m0 + r) * LG_STRIDE + k0 + c;
        uint32_t a[4];
        a[0] = __float_as_uint(lg[ai]);
        a[1] = __float_as_uint(lg[ai + 8 * LG_STRIDE]);
        a[2] = __float_as_uint(lg[ai + 4]);
        a[3] = __float_as_uint(lg[ai + 8 * LG_STRIDE + 4]);
        #pragma unroll
        for (int j = 0; j < 2; j++) {
            const int bi = (k0 + c) * SV_STRIDE + (wn2 * 2 + j) * 8 + r;
            uint32_t bb[2];
            bb[0] = __float_as_uint(sv[bi]);
            bb[1] = __float_as_uint(sv[bi + 4 * SV_STRIDE]);
            mma_tf32(oacc[j], a, bb);
        }
    }

    {
        const int rowA = m0 + r, rowB = m0 + 8 + r;
        #pragma unroll
        for (int j = 0; j < 2; j++) {
            const int col = (wn2 * 2 + j) * 8 + c * 2;
            if (rowA < N_TOK) {
                float2 v; v.x = tf32r(oacc[j][0]); v.y = tf32r(oacc[j][1]);
                *reinterpret_cast<float2*>(
                    &out[((size_t)b * N_TOK + rowA) * C_DIM + h * HD + col]) = v;
            }
            if (rowB < N_TOK) {
                float2 v; v.x = tf32r(oacc[j][2]); v.y = tf32r(oacc[j][3]);
                *reinterpret_cast<float2*>(
                    &out[((size_t)b * N_TOK + rowB) * C_DIM + h * HD + col]) = v;
            }
        }
    }
}

// ---------------------------------------------------------------------------
// Launch: round x/w -> QKV GEMM -> TC attention -> proj GEMM
// Inputs (metadata order): x, mask, qkv_w, qkv_b, rel_bias, proj_w, proj_b
// ---------------------------------------------------------------------------
extern "C" void kernel_launch(void* const* d_in, const int* in_sizes, int n_in,
                              void* d_out, int out_size)
{
    const float* x        = (const float*)d_in[0];
    const float* mask     = (const float*)d_in[1];
    const float* qkv_w    = (const float*)d_in[2];
    const float* qkv_b    = (const float*)d_in[3];
    const float* rel_bias = (const float*)d_in[4];
    const float* proj_w   = (const float*)d_in[5];
    const float* proj_b   = (const float*)d_in[6];
    float* out = (float*)d_out;

    float *qkv = nullptr, *attn = nullptr, *xr = nullptr, *qw = nullptr, *pw = nullptr;
    cudaGetSymbolAddress((void**)&qkv,  g_qkv);
    cudaGetSymbolAddress((void**)&attn, g_attn);
    cudaGetSymbolAddress((void**)&xr,   g_x);
    cudaGetSymbolAddress((void**)&qw,   g_qkvw);
    cudaGetSymbolAddress((void**)&pw,   g_projw);

    const int gemm_smem = SMEM_FLOATS * 4;        // 71680
    const int attn_smem = ATTN_SMEM_FLOATS * 4;   // 49920
    static bool attr_set = false;
    if (!attr_set) {
        cudaFuncSetAttribute(tf32_gemm_bias_kernel,
                             cudaFuncAttributeMaxDynamicSharedMemorySize, gemm_smem);
        cudaFuncSetAttribute(attn_tc_kernel,
                             cudaFuncAttributeMaxDynamicSharedMemorySize, attn_smem);
        attr_set = true;
    }

    // 0) Pre-round operands to tf32 (hoists cvt out of GEMM mainloops)
    {
        const int n4x = (int)((size_t)M_ROWS * C_DIM / 4);
        round_tf32_kernel<<<n4x / 256, 256>>>((const float4*)x, (float4*)xr, n4x);
        const int n4q = C_DIM * QKV_N / 4;
        round_tf32_kernel<<<(n4q + 255) / 256, 256>>>((const float4*)qkv_w, (float4*)qw, n4q);
        const int n4p = C_DIM * C_DIM / 4;
        round_tf32_kernel<<<(n4p + 255) / 256, 256>>>((const float4*)proj_w, (float4*)pw, n4p);
    }

    // 1) QKV projection: (401408 x 384) @ (384 x 1152) + b
    dim3 g1(QKV_N / 128, M_ROWS / 128);
    tf32_gemm_bias_kernel<<<g1, 256, gemm_smem>>>(M_ROWS, QKV_N, C_DIM,
                                                  xr, qw, qkv_b, qkv);

    // 2) Tensor-core window attention per (b, h)
    attn_tc_kernel<<<B_IMG * H_HEADS, 256, attn_smem>>>(qkv, rel_bias, mask, attn);

    // 3) Output projection: (401408 x 384) @ (384 x 384) + b
    dim3 g2(C_DIM / 128, M_ROWS / 128);
    tf32_gemm_bias_kernel<<<g2, 256, gemm_smem>>>(M_ROWS, C_DIM, C_DIM,
                                                  attn, pw, proj_b, out);
}